// round 8
// baseline (speedup 1.0000x reference)
#include <cuda_runtime.h>
#include <cuda_fp16.h>
#include <cstdint>

#define N_GENES 20000
#define UNITS   10000
#define DEG     32
#define BATCH   128

// |feature| transposed to [gene][batch] in fp16: 5.12 MB, L2-resident
// (and heavily L1-reused: each gene row is gathered ~16x on average).
__device__ __half g_featT[(size_t)N_GENES * BATCH];

__device__ __forceinline__ void cp_async16(uint32_t dst_smem, const void* src) {
    asm volatile("cp.async.ca.shared.global [%0], [%1], 16;"
                 :: "r"(dst_smem), "l"(src));
}

// ---------------------------------------------------------------------------
// K1: tiled transpose + fabs + fp16.  feature [128, 20000] -> featT [N, B]
// ---------------------------------------------------------------------------
__global__ void transpose_abs_kernel(const float* __restrict__ feature) {
    __shared__ float tile[32][33];               // tile[batch][gene]
    const int gx = blockIdx.x * 32;
    const int bx = blockIdx.y * 32;
    const int tx = threadIdx.x, ty = threadIdx.y;

#pragma unroll
    for (int k = 0; k < 32; k += 8)
        tile[ty + k][tx] = fabsf(feature[(size_t)(bx + ty + k) * N_GENES + (gx + tx)]);
    __syncthreads();

    const int t = ty * 32 + tx;
#pragma unroll
    for (int iter = 0; iter < 2; iter++) {
        const int tt  = iter * 256 + t;
        const int g_l = tt >> 4;                 // 0..31
        const int p   = tt & 15;                 // batch pair
        const __half2 h = __floats2half2_rn(tile[2 * p][g_l], tile[2 * p + 1][g_l]);
        *(__half2*)&g_featT[(size_t)(gx + g_l) * BATCH + bx + 2 * p] = h;
    }
}

// ---------------------------------------------------------------------------
// K2: gather-sum with cp.async staging. One warp per unit; the warp issues
// all 32 gene rows (8KB) as fire-and-forget cp.async (lane owns a 16B batch
// slice of gene 2p+hsel), then drains via wait_group + LDS.128 readback of
// its OWN bytes (no cross-lane visibility -> no syncwarp). half2 accumulate,
// fp32 flush every 8 genes, cross-half shfl_xor(16) combine.
// ---------------------------------------------------------------------------
__global__ void __launch_bounds__(128, 6) ppi_gather_kernel(
    const int*   __restrict__ ppi,     // int32 (JAX x64-disabled)
    const float* __restrict__ kern,
    const float* __restrict__ bias,
    float*       __restrict__ out)
{
    __shared__ __align__(16) __half rows[4][DEG][BATCH];   // 32 KB staging
    __shared__ float tile[4][BATCH + 4];

    const int lane   = threadIdx.x & 31;
    const int hlane  = lane & 15;                 // 16B batch-slice owner
    const int hsel   = lane >> 4;                 // 0: even gene, 1: odd gene
    const int warp   = threadIdx.x >> 5;          // 0..3
    const int u_base = blockIdx.x * 4;
    const int u      = u_base + warp;

    // Row byte-offset of ppi[u][lane] (row = 256B), coalesced 128B load.
    const int myoff = ppi[(size_t)u * DEG + lane] << 8;
    const char* gbase = (const char*)g_featT + hlane * 16;

    // smem slot for this lane's slice of gene (2p + hsel):
    // byte = p*512 + hsel*256 + hlane*16
    const uint32_t sbase =
        (uint32_t)__cvta_generic_to_shared(&rows[warp][0][0]) + hsel * 256 + hlane * 16;

    // Issue all 16 pairs (32 genes) in 4 commit groups — nothing lands in regs.
#pragma unroll
    for (int grp = 0; grp < 4; grp++) {
#pragma unroll
        for (int q = 0; q < 4; q++) {
            const int p   = grp * 4 + q;
            const int off = __shfl_sync(0xffffffffu, myoff, 2 * p + hsel);
            cp_async16(sbase + p * 512, gbase + off);
        }
        asm volatile("cp.async.commit_group;" ::: "memory");
    }

    float facc[8];
#pragma unroll
    for (int j = 0; j < 8; j++) facc[j] = 0.f;

#pragma unroll
    for (int wave = 0; wave < 2; wave++) {        // 2 flush periods x 8 pairs
        if (wave == 0) asm volatile("cp.async.wait_group 2;" ::: "memory");
        else           asm volatile("cp.async.wait_group 0;" ::: "memory");

        __half2 hacc[4];
#pragma unroll
        for (int j = 0; j < 4; j++) hacc[j] = __floats2half2_rn(0.f, 0.f);

#pragma unroll
        for (int q = 0; q < 8; q++) {
            const int p = wave * 8 + q;
            // Read back own slice: gene 2p+hsel, halves [hlane*8, +8)
            const uint4 raw = *(const uint4*)&rows[warp][2 * p + hsel][hlane * 8];
            hacc[0] = __hadd2(hacc[0], *(const __half2*)&raw.x);
            hacc[1] = __hadd2(hacc[1], *(const __half2*)&raw.y);
            hacc[2] = __hadd2(hacc[2], *(const __half2*)&raw.z);
            hacc[3] = __hadd2(hacc[3], *(const __half2*)&raw.w);
        }
#pragma unroll
        for (int j = 0; j < 4; j++) {
            const float2 f = __half22float2(hacc[j]);
            facc[2 * j]     += f.x;
            facc[2 * j + 1] += f.y;
        }
    }

    // Combine the two half-warps (disjoint gene subsets, same batch slice).
#pragma unroll
    for (int j = 0; j < 8; j++)
        facc[j] += __shfl_xor_sync(0xffffffffu, facc[j], 16);

    if (lane < 16) {
        const float kv = kern[u];
        const float bv = bias[u];
        float r[8];
#pragma unroll
        for (int j = 0; j < 8; j++)
            r[j] = tanhf(fmaf(facc[j], kv, bv));
        *(float4*)&tile[warp][hlane * 8]     = make_float4(r[0], r[1], r[2], r[3]);
        *(float4*)&tile[warp][hlane * 8 + 4] = make_float4(r[4], r[5], r[6], r[7]);
    }
    __syncthreads();

    // Output: 4-thread groups write contiguous 16B chunks of a batch row.
    for (int t = threadIdx.x; t < BATCH * 4; t += 128) {
        const int u_l = t & 3;
        const int b   = t >> 2;
        out[(size_t)b * UNITS + (u_base + u_l)] = tile[u_l][b];
    }
}

// ---------------------------------------------------------------------------
extern "C" void kernel_launch(void* const* d_in, const int* in_sizes, int n_in,
                              void* d_out, int out_size) {
    const float* feature = (const float*)d_in[0];
    const int*   ppi     = (const int*)d_in[1];
    const float* kern    = (const float*)d_in[2];
    const float* bias    = (const float*)d_in[3];
    float*       out     = (float*)d_out;

    dim3 tgrid(N_GENES / 32, BATCH / 32);   // (625, 4)
    dim3 tblock(32, 8);
    transpose_abs_kernel<<<tgrid, tblock>>>(feature);

    ppi_gather_kernel<<<UNITS / 4, 128>>>(ppi, kern, bias, out);  // 2500 CTAs
}

// round 9
// speedup vs baseline: 1.2716x; 1.2716x over previous
#include <cuda_runtime.h>
#include <cuda_fp16.h>
#include <cstdint>

#define N_GENES 20000
#define UNITS   10000
#define DEG     32
#define BATCH   128

// |feature| transposed to [gene][batch] in fp16: 5.12 MB, L2-resident.
// Row = 256B; each (unit, deg) gather reads one full row, coalesced.
// 82 MB of gather traffic vs ~6300 B/cyc achievable LTS cap => ~9-10us floor.
__device__ __half g_featT[(size_t)N_GENES * BATCH];

// ---------------------------------------------------------------------------
// K1: tiled transpose + fabs + fp16.  feature [128, 20000] -> featT [N, B]
// ---------------------------------------------------------------------------
__global__ void transpose_abs_kernel(const float* __restrict__ feature) {
    __shared__ float tile[32][33];               // tile[batch][gene]
    const int gx = blockIdx.x * 32;
    const int bx = blockIdx.y * 32;
    const int tx = threadIdx.x, ty = threadIdx.y;

#pragma unroll
    for (int k = 0; k < 32; k += 8)
        tile[ty + k][tx] = fabsf(feature[(size_t)(bx + ty + k) * N_GENES + (gx + tx)]);
    __syncthreads();

    const int t = ty * 32 + tx;
#pragma unroll
    for (int iter = 0; iter < 2; iter++) {
        const int tt  = iter * 256 + t;
        const int g_l = tt >> 4;                 // 0..31
        const int p   = tt & 15;                 // batch pair
        const __half2 h = __floats2half2_rn(tile[2 * p][g_l], tile[2 * p + 1][g_l]);
        *(__half2*)&g_featT[(size_t)(gx + g_l) * BATCH + bx + 2 * p] = h;
    }
}

// ---------------------------------------------------------------------------
// K2: gather-sum. One warp per unit. Each LDG.128 covers TWO gene rows
// (half-warp per gene, 16B batch slice per lane). 8 LDG.128 issued back-to-
// back per half-period (8KB in flight) -> only 2 exposed L2 round-trips per
// unit. half2 accumulate, fp32 flush per half; cross-half shfl_xor(16);
// smem-staged coalesced streaming output.
// ---------------------------------------------------------------------------
__global__ void __launch_bounds__(256, 4) ppi_gather_kernel(
    const int*   __restrict__ ppi,     // int32 (JAX x64-disabled)
    const float* __restrict__ kern,
    const float* __restrict__ bias,
    float*       __restrict__ out)
{
    __shared__ float tile[8][BATCH + 4];

    const int lane   = threadIdx.x & 31;
    const int hlane  = lane & 15;                 // batch-slice owner (16B)
    const int hsel   = lane >> 4;                 // 0: even gene, 1: odd gene
    const int warp   = threadIdx.x >> 5;
    const int u_base = blockIdx.x * 8;
    const int u      = u_base + warp;

    // Row byte-offset of ppi[u][lane] (row = 256B), coalesced 128B load.
    const int myoff = ppi[(size_t)u * DEG + lane] << 8;
    const char* base = (const char*)g_featT + hlane * 16;

    float facc[8];
#pragma unroll
    for (int j = 0; j < 8; j++) facc[j] = 0.f;

#pragma unroll
    for (int half = 0; half < 2; half++) {        // 2 flush periods x 16 genes
        // Issue all 8 LDG.128 of this half-period before consuming any.
        uint4 raw[8];
#pragma unroll
        for (int q = 0; q < 8; q++) {
            const int it  = half * 8 + q;         // 0..15
            const int off = __shfl_sync(0xffffffffu, myoff, 2 * it + hsel);
            raw[q] = *(const uint4*)(base + off);
        }

        __half2 hacc[4];
#pragma unroll
        for (int j = 0; j < 4; j++) hacc[j] = __floats2half2_rn(0.f, 0.f);
#pragma unroll
        for (int q = 0; q < 8; q++) {
            hacc[0] = __hadd2(hacc[0], *(const __half2*)&raw[q].x);
            hacc[1] = __hadd2(hacc[1], *(const __half2*)&raw[q].y);
            hacc[2] = __hadd2(hacc[2], *(const __half2*)&raw[q].z);
            hacc[3] = __hadd2(hacc[3], *(const __half2*)&raw[q].w);
        }
#pragma unroll
        for (int j = 0; j < 4; j++) {             // fp32 flush
            const float2 f = __half22float2(hacc[j]);
            facc[2 * j]     += f.x;
            facc[2 * j + 1] += f.y;
        }
    }

    // Combine the two half-warps (same batch slice, disjoint gene subsets).
#pragma unroll
    for (int j = 0; j < 8; j++)
        facc[j] += __shfl_xor_sync(0xffffffffu, facc[j], 16);

    if (lane < 16) {                              // conflict-free 512B row
        const float kv = kern[u];
        const float bv = bias[u];
        float r[8];
#pragma unroll
        for (int j = 0; j < 8; j++)
            r[j] = tanhf(fmaf(facc[j], kv, bv));
        *(float4*)&tile[warp][hlane * 8]     = make_float4(r[0], r[1], r[2], r[3]);
        *(float4*)&tile[warp][hlane * 8 + 4] = make_float4(r[4], r[5], r[6], r[7]);
    }
    __syncthreads();

    // Coalesced output: 8-thread groups write contiguous 32B chunks per row.
    // Streaming hint: out is write-once, keep it out of the hot L2 set.
    for (int t = threadIdx.x; t < BATCH * 8; t += 256) {
        const int u_l = t & 7;
        const int b   = t >> 3;
        __stcs(&out[(size_t)b * UNITS + (u_base + u_l)], tile[u_l][b]);
    }
}

// ---------------------------------------------------------------------------
extern "C" void kernel_launch(void* const* d_in, const int* in_sizes, int n_in,
                              void* d_out, int out_size) {
    const float* feature = (const float*)d_in[0];
    const int*   ppi     = (const int*)d_in[1];
    const float* kern    = (const float*)d_in[2];
    const float* bias    = (const float*)d_in[3];
    float*       out     = (float*)d_out;

    dim3 tgrid(N_GENES / 32, BATCH / 32);   // (625, 4)
    dim3 tblock(32, 8);
    transpose_abs_kernel<<<tgrid, tblock>>>(feature);

    ppi_gather_kernel<<<UNITS / 8, 256>>>(ppi, kern, bias, out);  // 1250 CTAs
}